// round 2
// baseline (speedup 1.0000x reference)
#include <cuda_runtime.h>
#include <cuda_bf16.h>

// DenseIouPred: 72x72 IoU map around ind[0], window radius r.
// Scatter inverts to per-pixel gather (valid offsets <-> in-range pixels 1:1,
// gather index == own flat index). R2: all loads hoisted unconditionally for
// max MLP (kills the ind->tgt->pred serialized latency chain), float4 I/O,
// 4 pixels per thread, fast divide.

#define W 72
#define H 72
#define NPIX (W * H)          // 5184
#define NV (NPIX / 4)         // 1296 float4 groups; plane stride = NV float4s

__device__ int g_default_radius = 10;

__global__ void dense_iou_kernel(const float4* __restrict__ out0,   // (4, W, H) as float4s
                                 const int*    __restrict__ ind,
                                 const float*  __restrict__ tgt,    // 4 floats, 16B-aligned
                                 const int*    __restrict__ radius_p,
                                 float4*       __restrict__ dst)    // (W, H) as float4s
{
    const int t = blockIdx.x * blockDim.x + threadIdx.x;
    if (t >= NV) return;

    // ---- issue ALL loads up front, fully independent (MLP ~ 7) ----
    const int    ind0 = __ldg(ind);
    const int    r    = __ldg(radius_p);
    const float4 tg   = *(const float4*)tgt;
    const float4 pl4  = out0[0 * NV + t];   // plane 0: pl
    const float4 pr4  = out0[1 * NV + t];   // plane 1: pr
    const float4 pt4  = out0[2 * NV + t];   // plane 2: pt
    const float4 pb4  = out0[3 * NV + t];   // plane 3: pb

    const int cw = ind0 % W;
    const int ch = ind0 / W;

    // 72 % 4 == 0 -> the 4 pixels of this thread share one row
    const int row  = t / (W / 4);           // t / 18
    const int col0 = (t % (W / 4)) * 4;

    const int   rh  = row - ch;
    const float frh = (float)rh;
    const float tht = tg.z + frh;
    const float thb = tg.w - frh;
    const bool  row_ok = (rh >= -r) && (rh <= r) && (tht >= 0.0f) && (thb >= 0.0f);

    float4 v = make_float4(0.f, 0.f, 0.f, 0.f);
    if (row_ok) {
        const float pls[4] = {pl4.x, pl4.y, pl4.z, pl4.w};
        const float prs[4] = {pr4.x, pr4.y, pr4.z, pr4.w};
        const float pts[4] = {pt4.x, pt4.y, pt4.z, pt4.w};
        const float pbs[4] = {pb4.x, pb4.y, pb4.z, pb4.w};
        float vs[4];
        #pragma unroll
        for (int j = 0; j < 4; j++) {
            const int   rw  = (col0 + j) - cw;
            const float frw = (float)rw;
            const float twl = tg.x + frw;
            const float twr = tg.y - frw;
            float vj = 0.0f;
            if (rw >= -r && rw <= r && twl >= 0.0f && twr >= 0.0f) {
                const float pl = pls[j], pr = prs[j], pt = pts[j], pb = pbs[j];
                const float target_area = (twl + twr) * (tht + thb);
                const float pred_area   = (pl + pr) * (pt + pb);
                const float w_int = fminf(pl, twl) + fminf(pr, twr);
                const float h_int = fminf(pb, thb) + fminf(pt, tht);
                const float area_int   = w_int * h_int;
                const float area_union = target_area + pred_area - area_int;
                vj = __fdividef(area_int + 1.0f, area_union + 1.0f);
            }
            vs[j] = vj;
        }
        v = make_float4(vs[0], vs[1], vs[2], vs[3]);
    }
    dst[t] = v;
}

extern "C" void kernel_launch(void* const* d_in, const int* in_sizes, int n_in,
                              void* d_out, int out_size)
{
    const float4* output = (const float4*)d_in[0];   // (128, 8, 4, 72, 72) fp32
    const int*    ind    = (const int*)   d_in[1];   // (128, 8, 1) int32
    const float*  target = (const float*) d_in[2];   // (128, 8, 4) fp32
    float4*       dst    = (float4*)d_out;           // (72, 72) fp32

    const int* radius = nullptr;
    if (n_in >= 4) {
        radius = (const int*)d_in[3];
    } else {
        void* p = nullptr;
        cudaGetSymbolAddress(&p, g_default_radius);  // no allocation; capture-safe
        radius = (const int*)p;
    }

    const int threads = 256;
    const int blocks  = (NV + threads - 1) / threads;   // 6 CTAs
    dense_iou_kernel<<<blocks, threads>>>(output, ind, target, radius, dst);
}